// round 16
// baseline (speedup 1.0000x reference)
#include <cuda_runtime.h>
#include <math_constants.h>

// Problem constants
#define SB 2048      // sequence length
#define NB 2         // batch
#define NH 16        // heads
#define HDIM 64      // head dim
#define DMODEL 1024  // model dim

// Scratch (device globals: allocation-free)
__device__ float g_q[(size_t)NB * NH * SB * HDIM];     // 16 MB, [b,h,s,d], pre-scaled by 0.125
__device__ float g_k[(size_t)NB * NH * SB * HDIM];     // 16 MB
__device__ float g_v[(size_t)NB * NH * SB * HDIM];     // 16 MB
__device__ float g_attn[(size_t)NB * SB * DMODEL];     // 16 MB, [b,s,h*d] == [4096,1024]

// ---------------------------------------------------------------------------
// SGEMM 128x128 tile, K-step 8, 256 threads, 8x8 outputs/thread.
// C[m,n] = sum_k A[m,k] * W[n,k]   (A row-major MxK, W row-major NxK)
// Two variants differing only in epilogue.
// ---------------------------------------------------------------------------

__global__ __launch_bounds__(256) void gemm_qkv_kernel(
    const float* __restrict__ X,      // [4096, 1024]
    const float* __restrict__ W,      // [3072, 1024]
    const float* __restrict__ bias)   // [3072]
{
    __shared__ float As[8][128];
    __shared__ float Bs[8][128];
    const int tid = threadIdx.x;
    const int tx = tid & 15;
    const int ty = tid >> 4;
    const int lr = tid >> 1;
    const int lc = (tid & 1) << 2;
    const int m0 = blockIdx.y * 128;
    const int n0 = blockIdx.x * 128;

    const float* Ag = X + (size_t)(m0 + lr) * 1024 + lc;
    const float* Bg = W + (size_t)(n0 + lr) * 1024 + lc;

    float acc[8][8];
#pragma unroll
    for (int i = 0; i < 8; i++)
#pragma unroll
        for (int j = 0; j < 8; j++) acc[i][j] = 0.f;

    float4 a = *(const float4*)(Ag);
    float4 b = *(const float4*)(Bg);

    for (int k0 = 0; k0 < 1024; k0 += 8) {
        As[lc + 0][lr] = a.x; As[lc + 1][lr] = a.y;
        As[lc + 2][lr] = a.z; As[lc + 3][lr] = a.w;
        Bs[lc + 0][lr] = b.x; Bs[lc + 1][lr] = b.y;
        Bs[lc + 2][lr] = b.z; Bs[lc + 3][lr] = b.w;
        __syncthreads();
        if (k0 + 8 < 1024) {
            a = *(const float4*)(Ag + k0 + 8);
            b = *(const float4*)(Bg + k0 + 8);
        }
#pragma unroll
        for (int kk = 0; kk < 8; kk++) {
            float av[8], bv[8];
            *(float4*)&av[0] = *(const float4*)&As[kk][ty * 8];
            *(float4*)&av[4] = *(const float4*)&As[kk][ty * 8 + 4];
            *(float4*)&bv[0] = *(const float4*)&Bs[kk][tx * 8];
            *(float4*)&bv[4] = *(const float4*)&Bs[kk][tx * 8 + 4];
#pragma unroll
            for (int i = 0; i < 8; i++)
#pragma unroll
                for (int j = 0; j < 8; j++)
                    acc[i][j] += av[i] * bv[j];
        }
        __syncthreads();
    }

    // Epilogue: scatter into head-major q/k/v, add bias, scale q by 0.125.
    const int n_base = n0 + tx * 8;           // stays inside one 64-wide head block
    const int part = n_base >> 10;            // 0=q 1=k 2=v (uniform per CTA)
    float* dst = (part == 0) ? g_q : (part == 1) ? g_k : g_v;
    const float mult = (part == 0) ? 0.125f : 1.0f;  // HEAD_DIM^-0.5 = 64^-0.5

    float bb[8];
#pragma unroll
    for (int j = 0; j < 8; j++) bb[j] = bias[n_base + j];
    const int h = (n_base >> 6) & 15;
    const int dcol = n_base & 63;

#pragma unroll
    for (int i = 0; i < 8; i++) {
        const int mrow = m0 + ty * 8 + i;
        const int batch = mrow >> 11;
        const int srow = mrow & 2047;
        const size_t off = (((size_t)batch * NH + h) * SB + srow) * HDIM + dcol;
        float4 o0, o1;
        o0.x = (acc[i][0] + bb[0]) * mult; o0.y = (acc[i][1] + bb[1]) * mult;
        o0.z = (acc[i][2] + bb[2]) * mult; o0.w = (acc[i][3] + bb[3]) * mult;
        o1.x = (acc[i][4] + bb[4]) * mult; o1.y = (acc[i][5] + bb[5]) * mult;
        o1.z = (acc[i][6] + bb[6]) * mult; o1.w = (acc[i][7] + bb[7]) * mult;
        *(float4*)(dst + off) = o0;
        *(float4*)(dst + off + 4) = o1;
    }
}

__global__ __launch_bounds__(256) void gemm_out_kernel(
    const float* __restrict__ W,      // [1024, 1024]
    const float* __restrict__ bias,   // [1024]
    float* __restrict__ out)          // [4096, 1024]
{
    __shared__ float As[8][128];
    __shared__ float Bs[8][128];
    const int tid = threadIdx.x;
    const int tx = tid & 15;
    const int ty = tid >> 4;
    const int lr = tid >> 1;
    const int lc = (tid & 1) << 2;
    const int m0 = blockIdx.y * 128;
    const int n0 = blockIdx.x * 128;

    const float* Ag = g_attn + (size_t)(m0 + lr) * 1024 + lc;
    const float* Bg = W + (size_t)(n0 + lr) * 1024 + lc;

    float acc[8][8];
#pragma unroll
    for (int i = 0; i < 8; i++)
#pragma unroll
        for (int j = 0; j < 8; j++) acc[i][j] = 0.f;

    float4 a = *(const float4*)(Ag);
    float4 b = *(const float4*)(Bg);

    for (int k0 = 0; k0 < 1024; k0 += 8) {
        As[lc + 0][lr] = a.x; As[lc + 1][lr] = a.y;
        As[lc + 2][lr] = a.z; As[lc + 3][lr] = a.w;
        Bs[lc + 0][lr] = b.x; Bs[lc + 1][lr] = b.y;
        Bs[lc + 2][lr] = b.z; Bs[lc + 3][lr] = b.w;
        __syncthreads();
        if (k0 + 8 < 1024) {
            a = *(const float4*)(Ag + k0 + 8);
            b = *(const float4*)(Bg + k0 + 8);
        }
#pragma unroll
        for (int kk = 0; kk < 8; kk++) {
            float av[8], bv[8];
            *(float4*)&av[0] = *(const float4*)&As[kk][ty * 8];
            *(float4*)&av[4] = *(const float4*)&As[kk][ty * 8 + 4];
            *(float4*)&bv[0] = *(const float4*)&Bs[kk][tx * 8];
            *(float4*)&bv[4] = *(const float4*)&Bs[kk][tx * 8 + 4];
#pragma unroll
            for (int i = 0; i < 8; i++)
#pragma unroll
                for (int j = 0; j < 8; j++)
                    acc[i][j] += av[i] * bv[j];
        }
        __syncthreads();
    }

    const int n_base = n0 + tx * 8;
    float bb[8];
#pragma unroll
    for (int j = 0; j < 8; j++) bb[j] = bias[n_base + j];

#pragma unroll
    for (int i = 0; i < 8; i++) {
        const int mrow = m0 + ty * 8 + i;
        float* po = out + (size_t)mrow * 1024 + n_base;
        float4 o0, o1;
        o0.x = acc[i][0] + bb[0]; o0.y = acc[i][1] + bb[1];
        o0.z = acc[i][2] + bb[2]; o0.w = acc[i][3] + bb[3];
        o1.x = acc[i][4] + bb[4]; o1.y = acc[i][5] + bb[5];
        o1.z = acc[i][6] + bb[6]; o1.w = acc[i][7] + bb[7];
        *(float4*)(po) = o0;
        *(float4*)(po + 4) = o1;
    }
}

// ---------------------------------------------------------------------------
// Flash attention, fp32. Mask: key j allowed iff j <= i + 256 (all past + 256
// future). 128 queries per CTA (1 per thread), KV tiles of 64 rows in smem,
// online softmax updated in 16-key chunks.
// ---------------------------------------------------------------------------
__global__ __launch_bounds__(128) void attn_kernel()
{
    __shared__ float Ks[64 * 64];
    __shared__ float Vs[64 * 64];

    const int bh = blockIdx.y;                         // b*16 + h
    const int qb = (int)gridDim.x - 1 - (int)blockIdx.x;  // heavy blocks first
    const int q0 = qb * 128;
    const int r = threadIdx.x;
    const int qi = q0 + r;

    // Load this thread's (pre-scaled) query row into registers.
    const float* qg = g_q + ((size_t)bh * SB + qi) * HDIM;
    float q[64];
#pragma unroll
    for (int i = 0; i < 16; i++) {
        float4 t = ((const float4*)qg)[i];
        q[4 * i + 0] = t.x; q[4 * i + 1] = t.y;
        q[4 * i + 2] = t.z; q[4 * i + 3] = t.w;
    }

    float acc[64];
#pragma unroll
    for (int d = 0; d < 64; d++) acc[d] = 0.f;
    float mrow = -1e30f;
    float lsum = 0.f;

    int kb_max = 2 * qb + 6;                 // tiles needed by last row of block
    if (kb_max > SB / 64) kb_max = SB / 64;
    const int kallow = qi + 256;             // keys with index <= kallow allowed

    const float* kg = g_k + (size_t)bh * SB * HDIM;
    const float* vg = g_v + (size_t)bh * SB * HDIM;

    for (int kb = 0; kb < kb_max; kb++) {
        // Cooperative tile load: 64x64 fp32 K and V (float4, coalesced).
        const float4* ksrc = (const float4*)(kg + kb * 64 * 64);
        const float4* vsrc = (const float4*)(vg + kb * 64 * 64);
#pragma unroll
        for (int i = 0; i < 8; i++) {
            const int idx = r + i * 128;
            ((float4*)Ks)[idx] = ksrc[idx];
            ((float4*)Vs)[idx] = vsrc[idx];
        }
        __syncthreads();

        const int jmax = kallow - kb * 64;   // allowed j <= jmax within tile
        if (jmax >= 0) {
            for (int jj = 0; jj < 64 && jj <= jmax; jj += 16) {
                float s[16];
#pragma unroll
                for (int j = 0; j < 16; j++) {
                    const float4* kr = (const float4*)(Ks + (jj + j) * 64);
                    float a0 = 0.f, a1 = 0.f, a2 = 0.f, a3 = 0.f;
#pragma unroll
                    for (int d4 = 0; d4 < 16; d4++) {
                        float4 kv = kr[d4];
                        a0 += q[4 * d4 + 0] * kv.x;
                        a1 += q[4 * d4 + 1] * kv.y;
                        a2 += q[4 * d4 + 2] * kv.z;
                        a3 += q[4 * d4 + 3] * kv.w;
                    }
                    float sv = (a0 + a1) + (a2 + a3);
                    s[j] = (jj + j <= jmax) ? sv : -CUDART_INF_F;
                }
                float tmax = s[0];
#pragma unroll
                for (int j = 1; j < 16; j++) tmax = fmaxf(tmax, s[j]);
                const float nm = fmaxf(mrow, tmax);
                const float corr = __expf(mrow - nm);
                mrow = nm;
                lsum *= corr;
#pragma unroll
                for (int d = 0; d < 64; d++) acc[d] *= corr;
#pragma unroll
                for (int j = 0; j < 16; j++) {
                    const float p = __expf(s[j] - nm);
                    lsum += p;
                    const float4* vr = (const float4*)(Vs + (jj + j) * 64);
#pragma unroll
                    for (int d4 = 0; d4 < 16; d4++) {
                        float4 vv = vr[d4];
                        acc[4 * d4 + 0] += p * vv.x;
                        acc[4 * d4 + 1] += p * vv.y;
                        acc[4 * d4 + 2] += p * vv.z;
                        acc[4 * d4 + 3] += p * vv.w;
                    }
                }
            }
        }
        __syncthreads();
    }

    const float inv = 1.f / lsum;
    const int batch = bh >> 4;
    const int h = bh & 15;
    float* og = g_attn + (((size_t)batch * SB + qi) * NH + h) * HDIM;
#pragma unroll
    for (int i = 0; i < 16; i++) {
        float4 o;
        o.x = acc[4 * i + 0] * inv;
        o.y = acc[4 * i + 1] * inv;
        o.z = acc[4 * i + 2] * inv;
        o.w = acc[4 * i + 3] * inv;
        ((float4*)og)[i] = o;
    }
}

// ---------------------------------------------------------------------------
extern "C" void kernel_launch(void* const* d_in, const int* in_sizes, int n_in,
                              void* d_out, int out_size)
{
    const float* x  = (const float*)d_in[0];   // [2,2048,1024]
    const float* w1 = (const float*)d_in[1];   // [3072,1024]
    const float* b1 = (const float*)d_in[2];   // [3072]
    const float* w2 = (const float*)d_in[3];   // [1024,1024]
    const float* b2 = (const float*)d_in[4];   // [1024]
    float* out = (float*)d_out;                // [2,2048,1024]

    gemm_qkv_kernel<<<dim3(3072 / 128, 4096 / 128), 256>>>(x, w1, b1);
    attn_kernel<<<dim3(SB / 128, NB * NH), 128>>>();
    gemm_out_kernel<<<dim3(1024 / 128, 4096 / 128), 256>>>(w2, b2, out);
}

// round 17
// speedup vs baseline: 1.0015x; 1.0015x over previous
#include <cuda_runtime.h>
#include <math_constants.h>

// Problem constants
#define SB 2048      // sequence length
#define NB 2         // batch
#define NH 16        // heads
#define HDIM 64      // head dim
#define DMODEL 1024  // model dim

// Scratch (device globals: allocation-free)
__device__ float g_q[(size_t)NB * NH * SB * HDIM];     // 16 MB, [b,h,s,d], pre-scaled by 0.125
__device__ float g_k[(size_t)NB * NH * SB * HDIM];     // 16 MB
__device__ float g_v[(size_t)NB * NH * SB * HDIM];     // 16 MB
__device__ float g_attn[(size_t)NB * SB * DMODEL];     // 16 MB, [b,s,h*d] == [4096,1024]

// ---------------------------------------------------------------------------
// SGEMM 128x128 tile, K-step 8, 256 threads, 8x8 outputs/thread.
// C[m,n] = sum_k A[m,k] * W[n,k]   (A row-major MxK, W row-major NxK)
// Two variants differing only in epilogue.
// ---------------------------------------------------------------------------

__global__ __launch_bounds__(256) void gemm_qkv_kernel(
    const float* __restrict__ X,      // [4096, 1024]
    const float* __restrict__ W,      // [3072, 1024]
    const float* __restrict__ bias)   // [3072]
{
    __shared__ float As[8][128];
    __shared__ float Bs[8][128];
    const int tid = threadIdx.x;
    const int tx = tid & 15;
    const int ty = tid >> 4;
    const int lr = tid >> 1;
    const int lc = (tid & 1) << 2;
    const int m0 = blockIdx.y * 128;
    const int n0 = blockIdx.x * 128;

    const float* Ag = X + (size_t)(m0 + lr) * 1024 + lc;
    const float* Bg = W + (size_t)(n0 + lr) * 1024 + lc;

    float acc[8][8];
#pragma unroll
    for (int i = 0; i < 8; i++)
#pragma unroll
        for (int j = 0; j < 8; j++) acc[i][j] = 0.f;

    float4 a = *(const float4*)(Ag);
    float4 b = *(const float4*)(Bg);

    for (int k0 = 0; k0 < 1024; k0 += 8) {
        As[lc + 0][lr] = a.x; As[lc + 1][lr] = a.y;
        As[lc + 2][lr] = a.z; As[lc + 3][lr] = a.w;
        Bs[lc + 0][lr] = b.x; Bs[lc + 1][lr] = b.y;
        Bs[lc + 2][lr] = b.z; Bs[lc + 3][lr] = b.w;
        __syncthreads();
        if (k0 + 8 < 1024) {
            a = *(const float4*)(Ag + k0 + 8);
            b = *(const float4*)(Bg + k0 + 8);
        }
#pragma unroll
        for (int kk = 0; kk < 8; kk++) {
            float av[8], bv[8];
            *(float4*)&av[0] = *(const float4*)&As[kk][ty * 8];
            *(float4*)&av[4] = *(const float4*)&As[kk][ty * 8 + 4];
            *(float4*)&bv[0] = *(const float4*)&Bs[kk][tx * 8];
            *(float4*)&bv[4] = *(const float4*)&Bs[kk][tx * 8 + 4];
#pragma unroll
            for (int i = 0; i < 8; i++)
#pragma unroll
                for (int j = 0; j < 8; j++)
                    acc[i][j] += av[i] * bv[j];
        }
        __syncthreads();
    }

    // Epilogue: scatter into head-major q/k/v, add bias, scale q by 0.125.
    const int n_base = n0 + tx * 8;           // stays inside one 64-wide head block
    const int part = n_base >> 10;            // 0=q 1=k 2=v (uniform per CTA)
    float* dst = (part == 0) ? g_q : (part == 1) ? g_k : g_v;
    const float mult = (part == 0) ? 0.125f : 1.0f;  // HEAD_DIM^-0.5 = 64^-0.5

    float bb[8];
#pragma unroll
    for (int j = 0; j < 8; j++) bb[j] = bias[n_base + j];
    const int h = (n_base >> 6) & 15;
    const int dcol = n_base & 63;

#pragma unroll
    for (int i = 0; i < 8; i++) {
        const int mrow = m0 + ty * 8 + i;
        const int batch = mrow >> 11;
        const int srow = mrow & 2047;
        const size_t off = (((size_t)batch * NH + h) * SB + srow) * HDIM + dcol;
        float4 o0, o1;
        o0.x = (acc[i][0] + bb[0]) * mult; o0.y = (acc[i][1] + bb[1]) * mult;
        o0.z = (acc[i][2] + bb[2]) * mult; o0.w = (acc[i][3] + bb[3]) * mult;
        o1.x = (acc[i][4] + bb[4]) * mult; o1.y = (acc[i][5] + bb[5]) * mult;
        o1.z = (acc[i][6] + bb[6]) * mult; o1.w = (acc[i][7] + bb[7]) * mult;
        *(float4*)(dst + off) = o0;
        *(float4*)(dst + off + 4) = o1;
    }
}

__global__ __launch_bounds__(256) void gemm_out_kernel(
    const float* __restrict__ W,      // [1024, 1024]
    const float* __restrict__ bias,   // [1024]
    float* __restrict__ out)          // [4096, 1024]
{
    __shared__ float As[8][128];
    __shared__ float Bs[8][128];
    const int tid = threadIdx.x;
    const int tx = tid & 15;
    const int ty = tid >> 4;
    const int lr = tid >> 1;
    const int lc = (tid & 1) << 2;
    const int m0 = blockIdx.y * 128;
    const int n0 = blockIdx.x * 128;

    const float* Ag = g_attn + (size_t)(m0 + lr) * 1024 + lc;
    const float* Bg = W + (size_t)(n0 + lr) * 1024 + lc;

    float acc[8][8];
#pragma unroll
    for (int i = 0; i < 8; i++)
#pragma unroll
        for (int j = 0; j < 8; j++) acc[i][j] = 0.f;

    float4 a = *(const float4*)(Ag);
    float4 b = *(const float4*)(Bg);

    for (int k0 = 0; k0 < 1024; k0 += 8) {
        As[lc + 0][lr] = a.x; As[lc + 1][lr] = a.y;
        As[lc + 2][lr] = a.z; As[lc + 3][lr] = a.w;
        Bs[lc + 0][lr] = b.x; Bs[lc + 1][lr] = b.y;
        Bs[lc + 2][lr] = b.z; Bs[lc + 3][lr] = b.w;
        __syncthreads();
        if (k0 + 8 < 1024) {
            a = *(const float4*)(Ag + k0 + 8);
            b = *(const float4*)(Bg + k0 + 8);
        }
#pragma unroll
        for (int kk = 0; kk < 8; kk++) {
            float av[8], bv[8];
            *(float4*)&av[0] = *(const float4*)&As[kk][ty * 8];
            *(float4*)&av[4] = *(const float4*)&As[kk][ty * 8 + 4];
            *(float4*)&bv[0] = *(const float4*)&Bs[kk][tx * 8];
            *(float4*)&bv[4] = *(const float4*)&Bs[kk][tx * 8 + 4];
#pragma unroll
            for (int i = 0; i < 8; i++)
#pragma unroll
                for (int j = 0; j < 8; j++)
                    acc[i][j] += av[i] * bv[j];
        }
        __syncthreads();
    }

    const int n_base = n0 + tx * 8;
    float bb[8];
#pragma unroll
    for (int j = 0; j < 8; j++) bb[j] = bias[n_base + j];

#pragma unroll
    for (int i = 0; i < 8; i++) {
        const int mrow = m0 + ty * 8 + i;
        float* po = out + (size_t)mrow * 1024 + n_base;
        float4 o0, o1;
        o0.x = acc[i][0] + bb[0]; o0.y = acc[i][1] + bb[1];
        o0.z = acc[i][2] + bb[2]; o0.w = acc[i][3] + bb[3];
        o1.x = acc[i][4] + bb[4]; o1.y = acc[i][5] + bb[5];
        o1.z = acc[i][6] + bb[6]; o1.w = acc[i][7] + bb[7];
        *(float4*)(po) = o0;
        *(float4*)(po + 4) = o1;
    }
}

// ---------------------------------------------------------------------------
// Flash attention, fp32. Mask: key j allowed iff j <= i + 256 (all past + 256
// future). 128 queries per CTA (1 per thread), KV tiles of 64 rows in smem,
// online softmax updated in 16-key chunks.
// ---------------------------------------------------------------------------
__global__ __launch_bounds__(128) void attn_kernel()
{
    __shared__ float Ks[64 * 64];
    __shared__ float Vs[64 * 64];

    const int bh = blockIdx.y;                         // b*16 + h
    const int qb = (int)gridDim.x - 1 - (int)blockIdx.x;  // heavy blocks first
    const int q0 = qb * 128;
    const int r = threadIdx.x;
    const int qi = q0 + r;

    // Load this thread's (pre-scaled) query row into registers.
    const float* qg = g_q + ((size_t)bh * SB + qi) * HDIM;
    float q[64];
#pragma unroll
    for (int i = 0; i < 16; i++) {
        float4 t = ((const float4*)qg)[i];
        q[4 * i + 0] = t.x; q[4 * i + 1] = t.y;
        q[4 * i + 2] = t.z; q[4 * i + 3] = t.w;
    }

    float acc[64];
#pragma unroll
    for (int d = 0; d < 64; d++) acc[d] = 0.f;
    float mrow = -1e30f;
    float lsum = 0.f;

    int kb_max = 2 * qb + 6;                 // tiles needed by last row of block
    if (kb_max > SB / 64) kb_max = SB / 64;
    const int kallow = qi + 256;             // keys with index <= kallow allowed

    const float* kg = g_k + (size_t)bh * SB * HDIM;
    const float* vg = g_v + (size_t)bh * SB * HDIM;

    for (int kb = 0; kb < kb_max; kb++) {
        // Cooperative tile load: 64x64 fp32 K and V (float4, coalesced).
        const float4* ksrc = (const float4*)(kg + kb * 64 * 64);
        const float4* vsrc = (const float4*)(vg + kb * 64 * 64);
#pragma unroll
        for (int i = 0; i < 8; i++) {
            const int idx = r + i * 128;
            ((float4*)Ks)[idx] = ksrc[idx];
            ((float4*)Vs)[idx] = vsrc[idx];
        }
        __syncthreads();

        const int jmax = kallow - kb * 64;   // allowed j <= jmax within tile
        if (jmax >= 0) {
            for (int jj = 0; jj < 64 && jj <= jmax; jj += 16) {
                float s[16];
#pragma unroll
                for (int j = 0; j < 16; j++) {
                    const float4* kr = (const float4*)(Ks + (jj + j) * 64);
                    float a0 = 0.f, a1 = 0.f, a2 = 0.f, a3 = 0.f;
#pragma unroll
                    for (int d4 = 0; d4 < 16; d4++) {
                        float4 kv = kr[d4];
                        a0 += q[4 * d4 + 0] * kv.x;
                        a1 += q[4 * d4 + 1] * kv.y;
                        a2 += q[4 * d4 + 2] * kv.z;
                        a3 += q[4 * d4 + 3] * kv.w;
                    }
                    float sv = (a0 + a1) + (a2 + a3);
                    s[j] = (jj + j <= jmax) ? sv : -CUDART_INF_F;
                }
                float tmax = s[0];
#pragma unroll
                for (int j = 1; j < 16; j++) tmax = fmaxf(tmax, s[j]);
                const float nm = fmaxf(mrow, tmax);
                const float corr = __expf(mrow - nm);
                mrow = nm;
                lsum *= corr;
#pragma unroll
                for (int d = 0; d < 64; d++) acc[d] *= corr;
#pragma unroll
                for (int j = 0; j < 16; j++) {
                    const float p = __expf(s[j] - nm);
                    lsum += p;
                    const float4* vr = (const float4*)(Vs + (jj + j) * 64);
#pragma unroll
                    for (int d4 = 0; d4 < 16; d4++) {
                        float4 vv = vr[d4];
                        acc[4 * d4 + 0] += p * vv.x;
                        acc[4 * d4 + 1] += p * vv.y;
                        acc[4 * d4 + 2] += p * vv.z;
                        acc[4 * d4 + 3] += p * vv.w;
                    }
                }
            }
        }
        __syncthreads();
    }

    const float inv = 1.f / lsum;
    const int batch = bh >> 4;
    const int h = bh & 15;
    float* og = g_attn + (((size_t)batch * SB + qi) * NH + h) * HDIM;
#pragma unroll
    for (int i = 0; i < 16; i++) {
        float4 o;
        o.x = acc[4 * i + 0] * inv;
        o.y = acc[4 * i + 1] * inv;
        o.z = acc[4 * i + 2] * inv;
        o.w = acc[4 * i + 3] * inv;
        ((float4*)og)[i] = o;
    }
}

// ---------------------------------------------------------------------------
extern "C" void kernel_launch(void* const* d_in, const int* in_sizes, int n_in,
                              void* d_out, int out_size)
{
    const float* x  = (const float*)d_in[0];   // [2,2048,1024]
    const float* w1 = (const float*)d_in[1];   // [3072,1024]
    const float* b1 = (const float*)d_in[2];   // [3072]
    const float* w2 = (const float*)d_in[3];   // [1024,1024]
    const float* b2 = (const float*)d_in[4];   // [1024]
    float* out = (float*)d_out;                // [2,2048,1024]

    gemm_qkv_kernel<<<dim3(3072 / 128, 4096 / 128), 256>>>(x, w1, b1);
    attn_kernel<<<dim3(SB / 128, NB * NH), 128>>>();
    gemm_out_kernel<<<dim3(1024 / 128, 4096 / 128), 256>>>(w2, b2, out);
}